// round 6
// baseline (speedup 1.0000x reference)
#include <cuda_runtime.h>
#include <math.h>
#include <stdint.h>

#define NQ    20
#define NL    4
#define BATCH 16
#define DIM   (1 << NQ)
#define TOTAL (BATCH * DIM)

#define CB      8                      // batches per chunk (hot set = 2*CB*4MB = 64MB < L2)
#define NCHUNK  (BATCH / CB)

// Per-chunk scratch ping-pong buffers (reused across chunks -> L2 stays hot)
__device__ float  g_bufA[CB * DIM];
__device__ float  g_bufB[CB * DIM];
__device__ float2 g_rf[NL * NQ];   // .x = ratio (|r|<=1), .y = form (0 or 1)
__device__ float  g_absC;          // |product of per-gate scales|

// ---------------------------------------------------------------------------
// Fast-Givens precompute.
//   form0 (|c|>=|s|): M = c*[[1,-t],[t,1]], t=s/c
//   form1 (|s|> |c|): M = s*[[u,-1],[1,u]], u=c/s
// ---------------------------------------------------------------------------
__global__ void sincos_kernel(const float* __restrict__ theta) {
    __shared__ float sc[NL * NQ];
    int i = threadIdx.x;
    if (i < NL * NQ) {
        float t = 0.5f * theta[i];
        float c = cosf(t), s = sinf(t);
        bool form = fabsf(s) > fabsf(c);
        g_rf[i] = make_float2(form ? (c / s) : (s / c), form ? 1.0f : 0.0f);
        sc[i] = form ? s : c;
    }
    __syncthreads();
    if (i == 0) {
        float p = 1.0f;
        for (int k = 0; k < NL * NQ; k++) p *= sc[k];
        g_absC = fabsf(p);
    }
}

// ---------------------------------------------------------------------------
// Fast-Givens butterflies (1 FFMA per element per stage).
// ---------------------------------------------------------------------------
__device__ __forceinline__ float xsign(float v, uint32_t sg) {
    return __uint_as_float(__float_as_uint(v) ^ sg);
}

__device__ __forceinline__ void stage_reg_fg(float e[32], int m, float2 rf) {
    float r = rf.x;
    if (rf.y == 0.0f) {
#pragma unroll
        for (int j = 0; j < 32; j++)
            if ((j & m) == 0) {
                float a = e[j], b = e[j | m];
                e[j]     = fmaf(-r, b, a);
                e[j | m] = fmaf( r, a, b);
            }
    } else {
#pragma unroll
        for (int j = 0; j < 32; j++)
            if ((j & m) == 0) {
                float a = e[j], b = e[j | m];
                e[j]     = fmaf(r, a, -b);
                e[j | m] = fmaf(r, b,  a);
            }
    }
}

__device__ __forceinline__ void stage_xlane_fg(float e[32], int kbit, float2 rf, int lane) {
    int bit = (lane >> kbit) & 1;
    if (rf.y == 0.0f) {
        float rs = bit ? rf.x : -rf.x;
#pragma unroll
        for (int j = 0; j < 32; j++) {
            float o = __shfl_xor_sync(0xffffffffu, e[j], 1 << kbit);
            e[j] = fmaf(rs, o, e[j]);
        }
    } else {
        float r = rf.x;
        uint32_t sg = bit ? 0u : 0x80000000u;
#pragma unroll
        for (int j = 0; j < 32; j++) {
            float o = __shfl_xor_sync(0xffffffffu, e[j], 1 << kbit);
            e[j] = fmaf(r, e[j], xsign(o, sg));
        }
    }
}

// gray decode (p such that p ^ (p>>1) = g)
__device__ __host__ __forceinline__ constexpr int gdec(int g) {
    int p = g;
    p ^= p >> 1; p ^= p >> 2; p ^= p >> 4; p ^= p >> 8; p ^= p >> 16;
    return p;
}

// ---------------------------------------------------------------------------
// HIGH kernel: qubits 0..4 (index bits 19:15). Register butterflies,
// coalesced, in-place capable. Pointers are pre-offset to the chunk.
// ---------------------------------------------------------------------------
__global__ void __launch_bounds__(512, 3) high_kernel(const float* __restrict__ in,
                                                      float* __restrict__ out,
                                                      int layer) {
    const int blk = blockIdx.x;   // CB*64 blocks: batch = blk>>6, window = blk&63
    const size_t off = ((size_t)(blk >> 6) << 20) + (size_t)(blk & 63) * 512 + threadIdx.x;

    float e[32];
    const float* p = in + off;
#pragma unroll
    for (int k = 0; k < 32; k++) e[k] = p[(size_t)k << 15];

    const float2* rf = g_rf + layer * NQ;
    stage_reg_fg(e, 1,  rf[4]);
    stage_reg_fg(e, 2,  rf[3]);
    stage_reg_fg(e, 4,  rf[2]);
    stage_reg_fg(e, 8,  rf[1]);
    stage_reg_fg(e, 16, rf[0]);

    float* q = out + off;
#pragma unroll
    for (int k = 0; k < 32; k++) q[(size_t)k << 15] = e[k];
}

// ---------------------------------------------------------------------------
// LOW kernel: qubits 5..19 inside contiguous 32768-float tiles.
// 1024 threads, 32 regs/thread. Phase1: 5 shuffle + 5 reg stages; smem
// transpose; Phase2: 5 reg stages. Store folds the CNOT-chain permutation
// (gray-decode scatter, one 128B line per warp); FINAL applies |C|*|.|.
// ---------------------------------------------------------------------------
template <bool FINAL>
__global__ void __launch_bounds__(1024, 1) low_kernel(const float* __restrict__ in,
                                                      float* __restrict__ out,
                                                      int layer) {
    extern __shared__ float sm[];          // 32768 floats = 128 KB
    const int t = threadIdx.x & 31;
    const int w = threadIdx.x >> 5;
    const size_t tbase = (size_t)blockIdx.x << 15;   // grid = CB*32 tiles

    float e[32];
    const float* p = in + tbase;
#pragma unroll
    for (int j = 0; j < 32; j++) e[j] = p[j * 1024 + w * 32 + t];

    const float2* rf = g_rf + layer * NQ;
    stage_xlane_fg(e, 0, rf[19], t);
    stage_xlane_fg(e, 1, rf[18], t);
    stage_xlane_fg(e, 2, rf[17], t);
    stage_xlane_fg(e, 3, rf[16], t);
    stage_xlane_fg(e, 4, rf[15], t);
    stage_reg_fg(e, 1,  rf[9]);
    stage_reg_fg(e, 2,  rf[8]);
    stage_reg_fg(e, 4,  rf[7]);
    stage_reg_fg(e, 8,  rf[6]);
    stage_reg_fg(e, 16, rf[5]);

#pragma unroll
    for (int j = 0; j < 32; j++) sm[j * 1024 + w * 32 + t] = e[j];
    __syncthreads();
#pragma unroll
    for (int j = 0; j < 32; j++) e[j] = sm[w * 1024 + j * 32 + t];

    stage_reg_fg(e, 1,  rf[14]);
    stage_reg_fg(e, 2,  rf[13]);
    stage_reg_fg(e, 4,  rf[12]);
    stage_reg_fg(e, 8,  rf[11]);
    stage_reg_fg(e, 16, rf[10]);

    const int    tile20 = (int)(tbase & (DIM - 1));
    const size_t bbase  = tbase & ~((size_t)(DIM - 1));
    const int    pbase  = gdec(tile20 + (w << 10) + t);
    if (FINAL) {
        const float absC = g_absC;
#pragma unroll
        for (int j = 0; j < 32; j++) {
            int pp = pbase ^ gdec(j << 5);
            out[bbase + pp] = fabsf(e[j]) * absC;
        }
    } else {
#pragma unroll
        for (int j = 0; j < 32; j++) {
            int pp = pbase ^ gdec(j << 5);
            out[bbase + pp] = e[j];
        }
    }
}

// ---------------------------------------------------------------------------
extern "C" void kernel_launch(void* const* d_in, const int* in_sizes, int n_in,
                              void* d_out, int out_size) {
    const float* x     = (const float*)d_in[0];
    const float* theta = (const float*)d_in[1];
    float*       out   = (float*)d_out;

    float *bA = nullptr, *bB = nullptr;
    cudaGetSymbolAddress((void**)&bA, g_bufA);
    cudaGetSymbolAddress((void**)&bB, g_bufB);

    const int SMEM = 32768 * sizeof(float);
    cudaFuncSetAttribute(low_kernel<false>, cudaFuncAttributeMaxDynamicSharedMemorySize, SMEM);
    cudaFuncSetAttribute(low_kernel<true>,  cudaFuncAttributeMaxDynamicSharedMemorySize, SMEM);

    sincos_kernel<<<1, 128>>>(theta);

    const int GH = CB * 64;   // HIGH grid per chunk
    const int GL = CB * 32;   // LOW grid per chunk

    for (int c = 0; c < NCHUNK; c++) {
        const float* xc = x   + ((size_t)c * CB << 20);
        float*       oc = out + ((size_t)c * CB << 20);

        high_kernel<<<GH, 512>>>(xc, bA, 0);
        low_kernel<false><<<GL, 1024, SMEM>>>(bA, bB, 0);
        high_kernel<<<GH, 512>>>(bB, bB, 1);
        low_kernel<false><<<GL, 1024, SMEM>>>(bB, bA, 1);
        high_kernel<<<GH, 512>>>(bA, bA, 2);
        low_kernel<false><<<GL, 1024, SMEM>>>(bA, bB, 2);
        high_kernel<<<GH, 512>>>(bB, bB, 3);
        low_kernel<true><<<GL, 1024, SMEM>>>(bB, oc, 3);
    }
}

// round 7
// speedup vs baseline: 1.0373x; 1.0373x over previous
#include <cuda_runtime.h>
#include <math.h>
#include <stdint.h>

#define NQ    20
#define NL    4
#define BATCH 16
#define DIM   (1 << NQ)

#define CB      8                      // batches per chunk
#define NCHUNK  (BATCH / CB)

__device__ float  g_bufA[CB * DIM];
__device__ float  g_bufB[CB * DIM];
__device__ float2 g_rf[NL * NQ];   // .x = ratio (|r|<=1), .y = form (0 or 1)
__device__ float  g_absC;          // |product of per-gate scales|

// ---------------------------------------------------------------------------
// Fast-Givens precompute.
//   form0 (|c|>=|s|): M = c*[[1,-t],[t,1]], t=s/c
//   form1 (|s|> |c|): M = s*[[u,-1],[1,u]], u=c/s
// ---------------------------------------------------------------------------
__global__ void sincos_kernel(const float* __restrict__ theta) {
    __shared__ float sc[NL * NQ];
    int i = threadIdx.x;
    if (i < NL * NQ) {
        float t = 0.5f * theta[i];
        float c = cosf(t), s = sinf(t);
        bool form = fabsf(s) > fabsf(c);
        g_rf[i] = make_float2(form ? (c / s) : (s / c), form ? 1.0f : 0.0f);
        sc[i] = form ? s : c;
    }
    __syncthreads();
    if (i == 0) {
        float p = 1.0f;
        for (int k = 0; k < NL * NQ; k++) p *= sc[k];
        g_absC = fabsf(p);
    }
}

// ---------------------------------------------------------------------------
// Fast-Givens butterflies. 'a' = role-0 element:
//   form0: a' = a - r*b ; b' = b + r*a
//   form1: a' = r*a - b ; b' = r*b + a
// ---------------------------------------------------------------------------
template <int N>
__device__ __forceinline__ void stage_fg(float* e, int m, float2 rf) {
    float r = rf.x;
    if (rf.y == 0.0f) {
#pragma unroll
        for (int j = 0; j < N; j++)
            if ((j & m) == 0) {
                float a = e[j], b = e[j | m];
                e[j]     = fmaf(-r, b, a);
                e[j | m] = fmaf( r, a, b);
            }
    } else {
#pragma unroll
        for (int j = 0; j < N; j++)
            if ((j & m) == 0) {
                float a = e[j], b = e[j | m];
                e[j]     = fmaf(r, a, -b);
                e[j | m] = fmaf(r, b,  a);
            }
    }
}

__device__ __forceinline__ float xsign(float v, uint32_t sg) {
    return __uint_as_float(__float_as_uint(v) ^ sg);
}

__device__ __forceinline__ void stage_xlane_fg(float e[32], int kbit, float2 rf, int lane) {
    int bit = (lane >> kbit) & 1;
    if (rf.y == 0.0f) {
        float rs = bit ? rf.x : -rf.x;
#pragma unroll
        for (int j = 0; j < 32; j++) {
            float o = __shfl_xor_sync(0xffffffffu, e[j], 1 << kbit);
            e[j] = fmaf(rs, o, e[j]);
        }
    } else {
        float r = rf.x;
        uint32_t sg = bit ? 0u : 0x80000000u;
#pragma unroll
        for (int j = 0; j < 32; j++) {
            float o = __shfl_xor_sync(0xffffffffu, e[j], 1 << kbit);
            e[j] = fmaf(r, e[j], xsign(o, sg));
        }
    }
}

// Conjugated H stage (P^-1 H P): couples u-pairs differing in bits {hb, hb-1};
// role(u) = parity(u >> hb). Enumerate pairs via u with bit hb == 0.
template <int HB>
__device__ __forceinline__ void conj_stage(float e[64], float2 rf) {
    const int mask = 3 << (HB - 1);
    float r = rf.x;
    bool f1 = (rf.y != 0.0f);
    if (!f1) {
#pragma unroll
        for (int u = 0; u < 64; u++)
            if ((u & (1 << HB)) == 0) {
                int v = u ^ mask;
                int ra = __popc(u >> HB) & 1;     // compile-time per u
                int ia = ra ? v : u;
                int ib = ra ? u : v;
                float a = e[ia], b = e[ib];
                e[ia] = fmaf(-r, b, a);
                e[ib] = fmaf( r, a, b);
            }
    } else {
#pragma unroll
        for (int u = 0; u < 64; u++)
            if ((u & (1 << HB)) == 0) {
                int v = u ^ mask;
                int ra = __popc(u >> HB) & 1;
                int ia = ra ? v : u;
                int ib = ra ? u : v;
                float a = e[ia], b = e[ib];
                e[ia] = fmaf(r, a, -b);
                e[ib] = fmaf(r, b,  a);
            }
    }
}

// gray decode (p such that p ^ (p>>1) = g)
__device__ __host__ __forceinline__ int gdec(int g) {
    int p = g;
    p ^= p >> 1; p ^= p >> 2; p ^= p >> 4; p ^= p >> 8; p ^= p >> 16;
    return p;
}
// 6-bit gray decode (compile-time for unrolled constants)
__device__ __forceinline__ int gd6(int u) {
    int p = u; p ^= p >> 1; p ^= p >> 2; p ^= p >> 4; return p & 63;
}

// ---------------------------------------------------------------------------
// HH kernel: applies H1 * P * H0. Thread owns orbit of g bits 19:14
// (64 elements, stride 2^14). H0 = plain stages on u bits 5:1 (qubit 5-i at
// u bit i). Then conjugated H1 stages. Store scatters with P:
//   gdec((u<<14)+pos) = (gd6(u)<<14) ^ (parity(u) ? gdec(pos)^0x3FFF : gdec(pos))
// ---------------------------------------------------------------------------
__global__ void __launch_bounds__(256, 2) hh_kernel(const float* __restrict__ in,
                                                    float* __restrict__ out) {
    const int blk = blockIdx.x;                   // CB*64 blocks
    const int pos = (blk & 63) * 256 + threadIdx.x;   // 14-bit position
    const size_t bbase = (size_t)(blk >> 6) << 20;

    float e[64];
    const float* pin = in + bbase + pos;
#pragma unroll
    for (int u = 0; u < 64; u++) e[u] = pin[u << 14];

    const float2* rf0 = g_rf;           // layer 0
    const float2* rf1 = g_rf + NQ;      // layer 1

    // H0: qubit q at u bit (5-q)
    stage_fg<64>(e, 32, rf0[0]);
    stage_fg<64>(e, 16, rf0[1]);
    stage_fg<64>(e,  8, rf0[2]);
    stage_fg<64>(e,  4, rf0[3]);
    stage_fg<64>(e,  2, rf0[4]);

    // conj(H1): qubit q -> HB = 5-q
    conj_stage<5>(e, rf1[0]);
    conj_stage<4>(e, rf1[1]);
    conj_stage<3>(e, rf1[2]);
    conj_stage<2>(e, rf1[3]);
    conj_stage<1>(e, rf1[4]);

    // scatter with P
    const int A  = gdec(pos);           // 14-bit
    float* pa = out + bbase + A;
    float* pb = out + bbase + (A ^ 0x3FFF);
#pragma unroll
    for (int u = 0; u < 64; u++) {
        int hi = gd6(u) << 14;          // compile-time per u
        if (__popc(u) & 1) pb[hi] = e[u];
        else               pa[hi] = e[u];
    }
}

// ---------------------------------------------------------------------------
// PH kernel: applies H_l * P. Gather at g = genc(p) = ((k<<15)^(k<<14)) ^
// (pos^(pos>>1)), plain H stages on k (qubit 4-b at k bit b), linear store.
// ---------------------------------------------------------------------------
__global__ void __launch_bounds__(512, 3) ph_kernel(const float* __restrict__ in,
                                                    float* __restrict__ out,
                                                    int layer) {
    const int blk = blockIdx.x;                   // CB*64 blocks
    const int pos = (blk & 63) * 512 + threadIdx.x;   // 15-bit position
    const size_t bbase = (size_t)(blk >> 6) << 20;
    const int G = pos ^ (pos >> 1);

    float e[32];
    const float* pin = in + bbase;
#pragma unroll
    for (int k = 0; k < 32; k++)
        e[k] = pin[((k << 15) ^ (k << 14)) ^ G];

    const float2* rf = g_rf + layer * NQ;
    stage_fg<32>(e, 1,  rf[4]);
    stage_fg<32>(e, 2,  rf[3]);
    stage_fg<32>(e, 4,  rf[2]);
    stage_fg<32>(e, 8,  rf[1]);
    stage_fg<32>(e, 16, rf[0]);

    float* pout = out + bbase + pos;
#pragma unroll
    for (int k = 0; k < 32; k++) pout[k << 15] = e[k];
}

// ---------------------------------------------------------------------------
// L kernel: qubits 5..19 inside contiguous 32768-float tiles, LINEAR I/O
// (in-place capable). FINAL variant folds last P + abs*|C| into the store.
// ---------------------------------------------------------------------------
template <bool FINAL>
__global__ void __launch_bounds__(1024, 1) low_kernel(const float* in,
                                                      float* out,
                                                      int layer) {
    extern __shared__ float sm[];          // 32768 floats = 128 KB
    const int t = threadIdx.x & 31;
    const int w = threadIdx.x >> 5;
    const size_t tbase = (size_t)blockIdx.x << 15;   // grid = CB*32 tiles

    float e[32];
    const float* p = in + tbase;
#pragma unroll
    for (int j = 0; j < 32; j++) e[j] = p[j * 1024 + w * 32 + t];

    const float2* rf = g_rf + layer * NQ;
    stage_xlane_fg(e, 0, rf[19], t);
    stage_xlane_fg(e, 1, rf[18], t);
    stage_xlane_fg(e, 2, rf[17], t);
    stage_xlane_fg(e, 3, rf[16], t);
    stage_xlane_fg(e, 4, rf[15], t);
    stage_fg<32>(e, 1,  rf[9]);
    stage_fg<32>(e, 2,  rf[8]);
    stage_fg<32>(e, 4,  rf[7]);
    stage_fg<32>(e, 8,  rf[6]);
    stage_fg<32>(e, 16, rf[5]);

#pragma unroll
    for (int j = 0; j < 32; j++) sm[j * 1024 + w * 32 + t] = e[j];
    __syncthreads();
#pragma unroll
    for (int j = 0; j < 32; j++) e[j] = sm[w * 1024 + j * 32 + t];

    stage_fg<32>(e, 1,  rf[14]);
    stage_fg<32>(e, 2,  rf[13]);
    stage_fg<32>(e, 4,  rf[12]);
    stage_fg<32>(e, 8,  rf[11]);
    stage_fg<32>(e, 16, rf[10]);

    if (FINAL) {
        const int    tile20 = (int)(tbase & (DIM - 1));
        const size_t bbase  = tbase & ~((size_t)(DIM - 1));
        const int    pbase  = gdec(tile20 + (w << 10) + t);
        const float  absC   = g_absC;
#pragma unroll
        for (int j = 0; j < 32; j++) {
            int pp = pbase ^ gdec(j << 5);
            out[bbase + pp] = fabsf(e[j]) * absC;
        }
    } else {
        float* q = out + tbase;
#pragma unroll
        for (int j = 0; j < 32; j++) q[w * 1024 + j * 32 + t] = e[j];
    }
}

// ---------------------------------------------------------------------------
extern "C" void kernel_launch(void* const* d_in, const int* in_sizes, int n_in,
                              void* d_out, int out_size) {
    const float* x     = (const float*)d_in[0];
    const float* theta = (const float*)d_in[1];
    float*       out   = (float*)d_out;

    float *bA = nullptr, *bB = nullptr;
    cudaGetSymbolAddress((void**)&bA, g_bufA);
    cudaGetSymbolAddress((void**)&bB, g_bufB);

    const int SMEM = 32768 * sizeof(float);
    cudaFuncSetAttribute(low_kernel<false>, cudaFuncAttributeMaxDynamicSharedMemorySize, SMEM);
    cudaFuncSetAttribute(low_kernel<true>,  cudaFuncAttributeMaxDynamicSharedMemorySize, SMEM);

    sincos_kernel<<<1, 128>>>(theta);

    const int GH = CB * 64;   // HH / PH grids
    const int GL = CB * 32;   // L grid

    for (int c = 0; c < NCHUNK; c++) {
        const float* xc = x   + ((size_t)c * CB << 20);
        float*       oc = out + ((size_t)c * CB << 20);

        low_kernel<false><<<GL, 1024, SMEM>>>(xc, bA, 0);   // L0
        hh_kernel<<<GH, 256>>>(bA, bB);                     // H1 * P * H0
        low_kernel<false><<<GL, 1024, SMEM>>>(bB, bB, 1);   // L1 (in-place)
        ph_kernel<<<GH, 512>>>(bB, bA, 2);                  // H2 * P
        low_kernel<false><<<GL, 1024, SMEM>>>(bA, bA, 2);   // L2 (in-place)
        ph_kernel<<<GH, 512>>>(bA, bB, 3);                  // H3 * P
        low_kernel<true><<<GL, 1024, SMEM>>>(bB, oc, 3);    // P * L3, abs*|C|
    }
}

// round 8
// speedup vs baseline: 1.1430x; 1.1019x over previous
#include <cuda_runtime.h>
#include <math.h>
#include <stdint.h>

#define NQ    20
#define NL    4
#define BATCH 16
#define DIM   (1 << NQ)

#define CB      8                      // batches per chunk
#define NCHUNK  (BATCH / CB)

__device__ float  g_bufA[CB * DIM];
__device__ float  g_bufB[CB * DIM];
__device__ float2 g_rf[NL * NQ];   // .x = ratio (|r|<=1), .y = form (0 or 1)
__device__ float  g_absC;          // |product of per-gate scales|

// ---------------------------------------------------------------------------
// Fast-Givens precompute.
//   form0 (|c|>=|s|): M = c*[[1,-t],[t,1]], t=s/c
//   form1 (|s|> |c|): M = s*[[u,-1],[1,u]], u=c/s
// ---------------------------------------------------------------------------
__global__ void sincos_kernel(const float* __restrict__ theta) {
    __shared__ float sc[NL * NQ];
    int i = threadIdx.x;
    if (i < NL * NQ) {
        float t = 0.5f * theta[i];
        float c = cosf(t), s = sinf(t);
        bool form = fabsf(s) > fabsf(c);
        g_rf[i] = make_float2(form ? (c / s) : (s / c), form ? 1.0f : 0.0f);
        sc[i] = form ? s : c;
    }
    __syncthreads();
    if (i == 0) {
        float p = 1.0f;
        for (int k = 0; k < NL * NQ; k++) p *= sc[k];
        g_absC = fabsf(p);
    }
}

// ---------------------------------------------------------------------------
// Fast-Givens butterflies. 'a' = role-0 element:
//   form0: a' = a - r*b ; b' = b + r*a
//   form1: a' = r*a - b ; b' = r*b + a
// ---------------------------------------------------------------------------
template <int N>
__device__ __forceinline__ void stage_fg(float* e, int m, float2 rf) {
    float r = rf.x;
    if (rf.y == 0.0f) {
#pragma unroll
        for (int j = 0; j < N; j++)
            if ((j & m) == 0) {
                float a = e[j], b = e[j | m];
                e[j]     = fmaf(-r, b, a);
                e[j | m] = fmaf( r, a, b);
            }
    } else {
#pragma unroll
        for (int j = 0; j < N; j++)
            if ((j & m) == 0) {
                float a = e[j], b = e[j | m];
                e[j]     = fmaf(r, a, -b);
                e[j | m] = fmaf(r, b,  a);
            }
    }
}

__device__ __forceinline__ float xsign(float v, uint32_t sg) {
    return __uint_as_float(__float_as_uint(v) ^ sg);
}

__device__ __forceinline__ void stage_xlane_fg(float e[32], int kbit, float2 rf, int lane) {
    int bit = (lane >> kbit) & 1;
    if (rf.y == 0.0f) {
        float rs = bit ? rf.x : -rf.x;
#pragma unroll
        for (int j = 0; j < 32; j++) {
            float o = __shfl_xor_sync(0xffffffffu, e[j], 1 << kbit);
            e[j] = fmaf(rs, o, e[j]);
        }
    } else {
        float r = rf.x;
        uint32_t sg = bit ? 0u : 0x80000000u;
#pragma unroll
        for (int j = 0; j < 32; j++) {
            float o = __shfl_xor_sync(0xffffffffu, e[j], 1 << kbit);
            e[j] = fmaf(r, e[j], xsign(o, sg));
        }
    }
}

// Conjugated H stage (P^-1 H P): couples u-pairs differing in bits {hb, hb-1};
// role(u) = parity(u >> hb).
template <int HB>
__device__ __forceinline__ void conj_stage(float e[64], float2 rf) {
    const int mask = 3 << (HB - 1);
    float r = rf.x;
    bool f1 = (rf.y != 0.0f);
    if (!f1) {
#pragma unroll
        for (int u = 0; u < 64; u++)
            if ((u & (1 << HB)) == 0) {
                int v = u ^ mask;
                int ra = __popc(u >> HB) & 1;
                int ia = ra ? v : u;
                int ib = ra ? u : v;
                float a = e[ia], b = e[ib];
                e[ia] = fmaf(-r, b, a);
                e[ib] = fmaf( r, a, b);
            }
    } else {
#pragma unroll
        for (int u = 0; u < 64; u++)
            if ((u & (1 << HB)) == 0) {
                int v = u ^ mask;
                int ra = __popc(u >> HB) & 1;
                int ia = ra ? v : u;
                int ib = ra ? u : v;
                float a = e[ia], b = e[ib];
                e[ia] = fmaf(r, a, -b);
                e[ib] = fmaf(r, b,  a);
            }
    }
}

// gray decode (p such that p ^ (p>>1) = g)
__device__ __host__ __forceinline__ int gdec(int g) {
    int p = g;
    p ^= p >> 1; p ^= p >> 2; p ^= p >> 4; p ^= p >> 8; p ^= p >> 16;
    return p;
}
__device__ __forceinline__ int gd6(int u) {
    int p = u; p ^= p >> 1; p ^= p >> 2; p ^= p >> 4; return p & 63;
}

// ---------------------------------------------------------------------------
// HH kernel: applies H1 * P * (H0 x R5_layer0). Orbit = g bits 19:14.
// ---------------------------------------------------------------------------
__global__ void __launch_bounds__(256, 2) hh_kernel(const float* __restrict__ in,
                                                    float* __restrict__ out) {
    const int blk = blockIdx.x;                   // CB*64
    const int pos = (blk & 63) * 256 + threadIdx.x;   // 14-bit position
    const size_t bbase = (size_t)(blk >> 6) << 20;

    float e[64];
    const float* pin = in + bbase + pos;
#pragma unroll
    for (int u = 0; u < 64; u++) e[u] = pin[u << 14];

    const float2* rf0 = g_rf;           // layer 0
    const float2* rf1 = g_rf + NQ;      // layer 1

    // layer-0 high stages: qubit q at u bit (5-q); qubit 5 (bit 14) = mask 1
    stage_fg<64>(e, 32, rf0[0]);
    stage_fg<64>(e, 16, rf0[1]);
    stage_fg<64>(e,  8, rf0[2]);
    stage_fg<64>(e,  4, rf0[3]);
    stage_fg<64>(e,  2, rf0[4]);
    stage_fg<64>(e,  1, rf0[5]);

    // conj(H1): qubit q -> HB = 5-q
    conj_stage<5>(e, rf1[0]);
    conj_stage<4>(e, rf1[1]);
    conj_stage<3>(e, rf1[2]);
    conj_stage<2>(e, rf1[3]);
    conj_stage<1>(e, rf1[4]);

    // scatter with P
    const int A  = gdec(pos);           // 14-bit
    float* pa = out + bbase + A;
    float* pb = out + bbase + (A ^ 0x3FFF);
#pragma unroll
    for (int u = 0; u < 64; u++) {
        int hi = gd6(u) << 14;
        if (__popc(u) & 1) pb[hi] = e[u];
        else               pa[hi] = e[u];
    }
}

// ---------------------------------------------------------------------------
// PH kernel: applies (H_l x R5_l) * P over qubits 0..5 (64-element orbit).
// Gather at g = genc(k<<14 | pos) = ((k<<14)^(k<<13)) ^ (pos^(pos>>1)).
// ---------------------------------------------------------------------------
__global__ void __launch_bounds__(256, 2) ph_kernel(const float* __restrict__ in,
                                                    float* __restrict__ out,
                                                    int layer) {
    const int blk = blockIdx.x;                   // CB*64
    const int pos = (blk & 63) * 256 + threadIdx.x;   // 14-bit position
    const size_t bbase = (size_t)(blk >> 6) << 20;
    const int G = pos ^ (pos >> 1);

    float e[64];
    const float* pin = in + bbase;
#pragma unroll
    for (int k = 0; k < 64; k++)
        e[k] = pin[((k << 14) ^ (k << 13)) ^ G];

    const float2* rf = g_rf + layer * NQ;
    // qubit q at k bit (5-q)
    stage_fg<64>(e, 32, rf[0]);
    stage_fg<64>(e, 16, rf[1]);
    stage_fg<64>(e,  8, rf[2]);
    stage_fg<64>(e,  4, rf[3]);
    stage_fg<64>(e,  2, rf[4]);
    stage_fg<64>(e,  1, rf[5]);

    float* pout = out + bbase + pos;
#pragma unroll
    for (int k = 0; k < 64; k++) pout[k << 14] = e[k];
}

// ---------------------------------------------------------------------------
// LOW14 kernel: qubits 6..19 inside contiguous 16384-float tiles.
// 512 threads x 32 regs, 64 KB smem -> 2 CTAs/SM.
// idx = j*512 + w*32 + t (j: bits 13:9, w: 8:5, t: 4:0); idx bit b <-> qubit 19-b.
// Phase1: shuffles q19..15; reg stages q6..10. Transpose swaps j[3:0] <-> w.
// Phase2: reg stages q11..14. FINAL folds last P + abs*|C| into scatter.
// ---------------------------------------------------------------------------
template <bool FINAL>
__global__ void __launch_bounds__(512, 2) low14_kernel(const float* in,
                                                       float* out,
                                                       int layer) {
    extern __shared__ float sm[];          // 16384 floats = 64 KB
    const int t = threadIdx.x & 31;
    const int w = threadIdx.x >> 5;        // 0..15
    const int blk = blockIdx.x;            // CB*64
    const int tile = blk & 63;
    const size_t bbase = (size_t)(blk >> 6) << 20;
    const size_t tbase = bbase + ((size_t)tile << 14);

    float e[32];
    const float* p = in + tbase;
#pragma unroll
    for (int j = 0; j < 32; j++) e[j] = p[j * 512 + w * 32 + t];

    const float2* rf = g_rf + layer * NQ;
    stage_xlane_fg(e, 0, rf[19], t);
    stage_xlane_fg(e, 1, rf[18], t);
    stage_xlane_fg(e, 2, rf[17], t);
    stage_xlane_fg(e, 3, rf[16], t);
    stage_xlane_fg(e, 4, rf[15], t);
    stage_fg<32>(e, 16, rf[6]);
    stage_fg<32>(e,  8, rf[7]);
    stage_fg<32>(e,  4, rf[8]);
    stage_fg<32>(e,  2, rf[9]);
    stage_fg<32>(e,  1, rf[10]);

#pragma unroll
    for (int j = 0; j < 32; j++) sm[j * 512 + w * 32 + t] = e[j];
    __syncthreads();
#pragma unroll
    for (int j = 0; j < 32; j++)
        e[j] = sm[(j >> 4) * 8192 + w * 512 + (j & 15) * 32 + t];

    // now e[j]: idx = ((j>>4)<<13) | (w<<9) | ((j&15)<<5) | t
    stage_fg<32>(e, 8, rf[11]);
    stage_fg<32>(e, 4, rf[12]);
    stage_fg<32>(e, 2, rf[13]);
    stage_fg<32>(e, 1, rf[14]);

    if (FINAL) {
        const int   pbase = gdec((tile << 14) | (w << 9) | t);
        const float absC  = g_absC;
#pragma unroll
        for (int j = 0; j < 32; j++) {
            int cj = gdec(((j >> 4) << 13) | ((j & 15) << 5));  // folds to const
            out[bbase + (pbase ^ cj)] = fabsf(e[j]) * absC;
        }
    } else {
        float* q = out + tbase;
#pragma unroll
        for (int j = 0; j < 32; j++)
            q[(j >> 4) * 8192 + w * 512 + (j & 15) * 32 + t] = e[j];
    }
}

// ---------------------------------------------------------------------------
// LOW15 kernel (layer 1 only): qubits 5..19, 32768-float tiles, linear,
// in-place. (q5 layer1 cannot be moved: its conj through P is non-local.)
// ---------------------------------------------------------------------------
__global__ void __launch_bounds__(1024, 1) low15_kernel(const float* in,
                                                        float* out,
                                                        int layer) {
    extern __shared__ float sm[];          // 32768 floats = 128 KB
    const int t = threadIdx.x & 31;
    const int w = threadIdx.x >> 5;
    const size_t tbase = (size_t)blockIdx.x << 15;   // grid = CB*32 tiles

    float e[32];
    const float* p = in + tbase;
#pragma unroll
    for (int j = 0; j < 32; j++) e[j] = p[j * 1024 + w * 32 + t];

    const float2* rf = g_rf + layer * NQ;
    stage_xlane_fg(e, 0, rf[19], t);
    stage_xlane_fg(e, 1, rf[18], t);
    stage_xlane_fg(e, 2, rf[17], t);
    stage_xlane_fg(e, 3, rf[16], t);
    stage_xlane_fg(e, 4, rf[15], t);
    stage_fg<32>(e, 1,  rf[9]);
    stage_fg<32>(e, 2,  rf[8]);
    stage_fg<32>(e, 4,  rf[7]);
    stage_fg<32>(e, 8,  rf[6]);
    stage_fg<32>(e, 16, rf[5]);

#pragma unroll
    for (int j = 0; j < 32; j++) sm[j * 1024 + w * 32 + t] = e[j];
    __syncthreads();
#pragma unroll
    for (int j = 0; j < 32; j++) e[j] = sm[w * 1024 + j * 32 + t];

    stage_fg<32>(e, 1,  rf[14]);
    stage_fg<32>(e, 2,  rf[13]);
    stage_fg<32>(e, 4,  rf[12]);
    stage_fg<32>(e, 8,  rf[11]);
    stage_fg<32>(e, 16, rf[10]);

    float* q = out + tbase;
#pragma unroll
    for (int j = 0; j < 32; j++) q[w * 1024 + j * 32 + t] = e[j];
}

// ---------------------------------------------------------------------------
extern "C" void kernel_launch(void* const* d_in, const int* in_sizes, int n_in,
                              void* d_out, int out_size) {
    const float* x     = (const float*)d_in[0];
    const float* theta = (const float*)d_in[1];
    float*       out   = (float*)d_out;

    float *bA = nullptr, *bB = nullptr;
    cudaGetSymbolAddress((void**)&bA, g_bufA);
    cudaGetSymbolAddress((void**)&bB, g_bufB);

    const int SM14 = 16384 * sizeof(float);
    const int SM15 = 32768 * sizeof(float);
    cudaFuncSetAttribute(low14_kernel<false>, cudaFuncAttributeMaxDynamicSharedMemorySize, SM14);
    cudaFuncSetAttribute(low14_kernel<true>,  cudaFuncAttributeMaxDynamicSharedMemorySize, SM14);
    cudaFuncSetAttribute(low15_kernel,        cudaFuncAttributeMaxDynamicSharedMemorySize, SM15);

    sincos_kernel<<<1, 128>>>(theta);

    const int GH  = CB * 64;   // hh / ph / low14 grids
    const int GL  = CB * 32;   // low15 grid

    for (int c = 0; c < NCHUNK; c++) {
        const float* xc = x   + ((size_t)c * CB << 20);
        float*       oc = out + ((size_t)c * CB << 20);

        low14_kernel<false><<<GH, 512, SM14>>>(xc, bA, 0);  // L0 (q6..19)
        hh_kernel<<<GH, 256>>>(bA, bB);                     // H1 * P * (H0,R5L0)
        low15_kernel<<<GL, 1024, SM15>>>(bB, bB, 1);        // L1 (q5..19, in-place)
        ph_kernel<<<GH, 256>>>(bB, bA, 2);                  // (H2,R5L2) * P
        low14_kernel<false><<<GH, 512, SM14>>>(bA, bA, 2);  // L2 (in-place)
        ph_kernel<<<GH, 256>>>(bA, bB, 3);                  // (H3,R5L3) * P
        low14_kernel<true><<<GH, 512, SM14>>>(bB, oc, 3);   // P * L3, abs*|C|
    }
}

// round 9
// speedup vs baseline: 1.1432x; 1.0002x over previous
#include <cuda_runtime.h>
#include <math.h>
#include <stdint.h>

#define NQ    20
#define NL    4
#define BATCH 16
#define DIM   (1 << NQ)

#define CB      8                      // batches per chunk
#define NCHUNK  (BATCH / CB)

__device__ float  g_bufA[CB * DIM];
__device__ float  g_bufB[CB * DIM];
__device__ float2 g_rf[NL * NQ];   // .x = ratio (|r|<=1), .y = form (0 or 1)
__device__ float  g_absC;          // |product of per-gate scales|

// ---------------------------------------------------------------------------
// Fast-Givens precompute.
//   form0 (|c|>=|s|): M = c*[[1,-t],[t,1]], t=s/c
//   form1 (|s|> |c|): M = s*[[u,-1],[1,u]], u=c/s
// ---------------------------------------------------------------------------
__global__ void sincos_kernel(const float* __restrict__ theta) {
    __shared__ float sc[NL * NQ];
    int i = threadIdx.x;
    if (i < NL * NQ) {
        float t = 0.5f * theta[i];
        float c = cosf(t), s = sinf(t);
        bool form = fabsf(s) > fabsf(c);
        g_rf[i] = make_float2(form ? (c / s) : (s / c), form ? 1.0f : 0.0f);
        sc[i] = form ? s : c;
    }
    __syncthreads();
    if (i == 0) {
        float p = 1.0f;
        for (int k = 0; k < NL * NQ; k++) p *= sc[k];
        g_absC = fabsf(p);
    }
}

// ---------------------------------------------------------------------------
// Fast-Givens butterflies. 'a' = role-0 element:
//   form0: a' = a - r*b ; b' = b + r*a
//   form1: a' = r*a - b ; b' = r*b + a
// ---------------------------------------------------------------------------
template <int N>
__device__ __forceinline__ void stage_fg(float* e, int m, float2 rf) {
    float r = rf.x;
    if (rf.y == 0.0f) {
#pragma unroll
        for (int j = 0; j < N; j++)
            if ((j & m) == 0) {
                float a = e[j], b = e[j | m];
                e[j]     = fmaf(-r, b, a);
                e[j | m] = fmaf( r, a, b);
            }
    } else {
#pragma unroll
        for (int j = 0; j < N; j++)
            if ((j & m) == 0) {
                float a = e[j], b = e[j | m];
                e[j]     = fmaf(r, a, -b);
                e[j | m] = fmaf(r, b,  a);
            }
    }
}

__device__ __forceinline__ float xsign(float v, uint32_t sg) {
    return __uint_as_float(__float_as_uint(v) ^ sg);
}

__device__ __forceinline__ void stage_xlane_fg(float e[32], int kbit, float2 rf, int lane) {
    int bit = (lane >> kbit) & 1;
    if (rf.y == 0.0f) {
        float rs = bit ? rf.x : -rf.x;
#pragma unroll
        for (int j = 0; j < 32; j++) {
            float o = __shfl_xor_sync(0xffffffffu, e[j], 1 << kbit);
            e[j] = fmaf(rs, o, e[j]);
        }
    } else {
        float r = rf.x;
        uint32_t sg = bit ? 0u : 0x80000000u;
#pragma unroll
        for (int j = 0; j < 32; j++) {
            float o = __shfl_xor_sync(0xffffffffu, e[j], 1 << kbit);
            e[j] = fmaf(r, e[j], xsign(o, sg));
        }
    }
}

// Conjugated H stage (P^-1 H P): couples u-pairs differing in bits {hb, hb-1};
// role(u) = parity(u >> hb).
template <int HB>
__device__ __forceinline__ void conj_stage(float e[64], float2 rf) {
    const int mask = 3 << (HB - 1);
    float r = rf.x;
    bool f1 = (rf.y != 0.0f);
    if (!f1) {
#pragma unroll
        for (int u = 0; u < 64; u++)
            if ((u & (1 << HB)) == 0) {
                int v = u ^ mask;
                int ra = __popc(u >> HB) & 1;
                int ia = ra ? v : u;
                int ib = ra ? u : v;
                float a = e[ia], b = e[ib];
                e[ia] = fmaf(-r, b, a);
                e[ib] = fmaf( r, a, b);
            }
    } else {
#pragma unroll
        for (int u = 0; u < 64; u++)
            if ((u & (1 << HB)) == 0) {
                int v = u ^ mask;
                int ra = __popc(u >> HB) & 1;
                int ia = ra ? v : u;
                int ib = ra ? u : v;
                float a = e[ia], b = e[ib];
                e[ia] = fmaf(r, a, -b);
                e[ib] = fmaf(r, b,  a);
            }
    }
}

// Conjugated R5(layer1) stage inside hh: couples g bits {14,13} = (reg bit 0,
// lane bit 0). Partner of e[u] is shfl_xor(e[u^1], 1). Role 'a' = p-bit-14
// = parity(u) == 0. Both shuffles of a pair are read before either write.
__device__ __forceinline__ void conj_r5_stage(float e[64], float2 rf) {
    float r = rf.x;
    bool f1 = (rf.y != 0.0f);
#pragma unroll
    for (int u = 0; u < 64; u += 2) {
        float o0 = __shfl_xor_sync(0xffffffffu, e[u + 1], 1);  // partner of e[u]
        float o1 = __shfl_xor_sync(0xffffffffu, e[u],     1);  // partner of e[u+1]
        bool aFirst = ((__popc(u) & 1) == 0);   // e[u]='a' iff parity(u)==0
        if (!f1) {
            if (aFirst) {
                e[u]     = fmaf(-r, o0, e[u]);
                e[u + 1] = fmaf( r, o1, e[u + 1]);
            } else {
                e[u]     = fmaf( r, o0, e[u]);
                e[u + 1] = fmaf(-r, o1, e[u + 1]);
            }
        } else {
            if (aFirst) {
                e[u]     = fmaf(r, e[u],     -o0);
                e[u + 1] = fmaf(r, e[u + 1],  o1);
            } else {
                e[u]     = fmaf(r, e[u],      o0);
                e[u + 1] = fmaf(r, e[u + 1], -o1);
            }
        }
    }
}

// gray decode (p such that p ^ (p>>1) = g)
__device__ __host__ __forceinline__ int gdec(int g) {
    int p = g;
    p ^= p >> 1; p ^= p >> 2; p ^= p >> 4; p ^= p >> 8; p ^= p >> 16;
    return p;
}
__device__ __forceinline__ int gd6(int u) {
    int p = u; p ^= p >> 1; p ^= p >> 2; p ^= p >> 4; return p & 63;
}

// ---------------------------------------------------------------------------
// HH kernel: applies (R5_l1) * H1 * P * (H0 x R5_l0). Orbit = g bits 19:14
// in registers; pos bit 13 lives on lane bit 0 so conj(R5_l1) is warp-local.
//   pos = (t0<<13) | (sub<<7) | (w<<4) | t[4:1]
// ---------------------------------------------------------------------------
__global__ void __launch_bounds__(256, 2) hh_kernel(const float* __restrict__ in,
                                                    float* __restrict__ out) {
    const int blk = blockIdx.x;                   // CB*64
    const int tid = threadIdx.x;
    const int t0  = tid & 1;
    const int w   = tid >> 5;                     // 0..7
    const int tl  = (tid >> 1) & 15;              // pos bits 3:0
    const int sub = blk & 63;
    const int pos = (t0 << 13) | (sub << 7) | (w << 4) | tl;
    const size_t bbase = (size_t)(blk >> 6) << 20;

    float e[64];
    const float* pin = in + bbase + pos;
#pragma unroll
    for (int u = 0; u < 64; u++) e[u] = pin[u << 14];

    const float2* rf0 = g_rf;           // layer 0
    const float2* rf1 = g_rf + NQ;      // layer 1

    // layer-0 high stages (g-domain, plain): qubit q at u bit (5-q)
    stage_fg<64>(e, 32, rf0[0]);
    stage_fg<64>(e, 16, rf0[1]);
    stage_fg<64>(e,  8, rf0[2]);
    stage_fg<64>(e,  4, rf0[3]);
    stage_fg<64>(e,  2, rf0[4]);
    stage_fg<64>(e,  1, rf0[5]);

    // conj(H1): qubit q -> HB = 5-q
    conj_stage<5>(e, rf1[0]);
    conj_stage<4>(e, rf1[1]);
    conj_stage<3>(e, rf1[2]);
    conj_stage<2>(e, rf1[3]);
    conj_stage<1>(e, rf1[4]);
    // conj(R5 layer1): g bits {14,13}
    conj_r5_stage(e, rf1[5]);

    // scatter with P
    const int A  = gdec(pos);           // 14-bit
    float* pa = out + bbase + A;
    float* pb = out + bbase + (A ^ 0x3FFF);
#pragma unroll
    for (int u = 0; u < 64; u++) {
        int hi = gd6(u) << 14;
        if (__popc(u) & 1) pb[hi] = e[u];
        else               pa[hi] = e[u];
    }
}

// ---------------------------------------------------------------------------
// PH kernel: applies (H_l x R5_l) * P over qubits 0..5 (64-element orbit).
// Gather at g = genc(k<<14 | pos) = ((k<<14)^(k<<13)) ^ (pos^(pos>>1)).
// ---------------------------------------------------------------------------
__global__ void __launch_bounds__(256, 2) ph_kernel(const float* __restrict__ in,
                                                    float* __restrict__ out,
                                                    int layer) {
    const int blk = blockIdx.x;                   // CB*64
    const int pos = (blk & 63) * 256 + threadIdx.x;   // 14-bit position
    const size_t bbase = (size_t)(blk >> 6) << 20;
    const int G = pos ^ (pos >> 1);

    float e[64];
    const float* pin = in + bbase;
#pragma unroll
    for (int k = 0; k < 64; k++)
        e[k] = pin[((k << 14) ^ (k << 13)) ^ G];

    const float2* rf = g_rf + layer * NQ;
    // qubit q at k bit (5-q)
    stage_fg<64>(e, 32, rf[0]);
    stage_fg<64>(e, 16, rf[1]);
    stage_fg<64>(e,  8, rf[2]);
    stage_fg<64>(e,  4, rf[3]);
    stage_fg<64>(e,  2, rf[4]);
    stage_fg<64>(e,  1, rf[5]);

    float* pout = out + bbase + pos;
#pragma unroll
    for (int k = 0; k < 64; k++) pout[k << 14] = e[k];
}

// ---------------------------------------------------------------------------
// LOW14 kernel: qubits 6..19 inside contiguous 16384-float tiles.
// 512 threads x 32 regs, 64 KB smem -> 2 CTAs/SM.
// idx = j*512 + w*32 + t (j: bits 13:9, w: 8:5, t: 4:0); idx bit b <-> qubit 19-b.
// Phase1: shuffles q19..15; reg stages q6..10. Transpose swaps j[3:0] <-> w.
// Phase2: reg stages q11..14. FINAL folds last P + abs*|C| into scatter.
// ---------------------------------------------------------------------------
template <bool FINAL>
__global__ void __launch_bounds__(512, 2) low14_kernel(const float* in,
                                                       float* out,
                                                       int layer) {
    extern __shared__ float sm[];          // 16384 floats = 64 KB
    const int t = threadIdx.x & 31;
    const int w = threadIdx.x >> 5;        // 0..15
    const int blk = blockIdx.x;            // CB*64
    const int tile = blk & 63;
    const size_t bbase = (size_t)(blk >> 6) << 20;
    const size_t tbase = bbase + ((size_t)tile << 14);

    float e[32];
    const float* p = in + tbase;
#pragma unroll
    for (int j = 0; j < 32; j++) e[j] = p[j * 512 + w * 32 + t];

    const float2* rf = g_rf + layer * NQ;
    stage_xlane_fg(e, 0, rf[19], t);
    stage_xlane_fg(e, 1, rf[18], t);
    stage_xlane_fg(e, 2, rf[17], t);
    stage_xlane_fg(e, 3, rf[16], t);
    stage_xlane_fg(e, 4, rf[15], t);
    stage_fg<32>(e, 16, rf[6]);
    stage_fg<32>(e,  8, rf[7]);
    stage_fg<32>(e,  4, rf[8]);
    stage_fg<32>(e,  2, rf[9]);
    stage_fg<32>(e,  1, rf[10]);

#pragma unroll
    for (int j = 0; j < 32; j++) sm[j * 512 + w * 32 + t] = e[j];
    __syncthreads();
#pragma unroll
    for (int j = 0; j < 32; j++)
        e[j] = sm[(j >> 4) * 8192 + w * 512 + (j & 15) * 32 + t];

    // now e[j]: idx = ((j>>4)<<13) | (w<<9) | ((j&15)<<5) | t
    stage_fg<32>(e, 8, rf[11]);
    stage_fg<32>(e, 4, rf[12]);
    stage_fg<32>(e, 2, rf[13]);
    stage_fg<32>(e, 1, rf[14]);

    if (FINAL) {
        const int   pbase = gdec((tile << 14) | (w << 9) | t);
        const float absC  = g_absC;
#pragma unroll
        for (int j = 0; j < 32; j++) {
            int cj = gdec(((j >> 4) << 13) | ((j & 15) << 5));  // folds to const
            out[bbase + (pbase ^ cj)] = fabsf(e[j]) * absC;
        }
    } else {
        float* q = out + tbase;
#pragma unroll
        for (int j = 0; j < 32; j++)
            q[(j >> 4) * 8192 + w * 512 + (j & 15) * 32 + t] = e[j];
    }
}

// ---------------------------------------------------------------------------
extern "C" void kernel_launch(void* const* d_in, const int* in_sizes, int n_in,
                              void* d_out, int out_size) {
    const float* x     = (const float*)d_in[0];
    const float* theta = (const float*)d_in[1];
    float*       out   = (float*)d_out;

    float *bA = nullptr, *bB = nullptr;
    cudaGetSymbolAddress((void**)&bA, g_bufA);
    cudaGetSymbolAddress((void**)&bB, g_bufB);

    const int SM14 = 16384 * sizeof(float);
    cudaFuncSetAttribute(low14_kernel<false>, cudaFuncAttributeMaxDynamicSharedMemorySize, SM14);
    cudaFuncSetAttribute(low14_kernel<true>,  cudaFuncAttributeMaxDynamicSharedMemorySize, SM14);

    sincos_kernel<<<1, 128>>>(theta);

    const int GH = CB * 64;   // all grids

    for (int c = 0; c < NCHUNK; c++) {
        const float* xc = x   + ((size_t)c * CB << 20);
        float*       oc = out + ((size_t)c * CB << 20);

        low14_kernel<false><<<GH, 512, SM14>>>(xc, bA, 0);  // L0 (q6..19)
        hh_kernel<<<GH, 256>>>(bA, bB);                     // R5l1*H1*P*(H0,R5l0)
        low14_kernel<false><<<GH, 512, SM14>>>(bB, bB, 1);  // L1 (q6..19, in-place)
        ph_kernel<<<GH, 256>>>(bB, bA, 2);                  // (H2,R5l2) * P
        low14_kernel<false><<<GH, 512, SM14>>>(bA, bA, 2);  // L2 (in-place)
        ph_kernel<<<GH, 256>>>(bA, bB, 3);                  // (H3,R5l3) * P
        low14_kernel<true><<<GH, 512, SM14>>>(bB, oc, 3);   // P * L3, abs*|C|
    }
}